// round 6
// baseline (speedup 1.0000x reference)
#include <cuda_runtime.h>
#include <cstdint>

#define Bn 8192
#define Fn 4096
#define Kn 64
#define MT 64            // rows per CTA -> 128 CTAs
#define KC 32            // F-depth per stage
#define NT 512           // 16 warps: 4M x 4N
#define STAGES 8
#define NTILES (Fn / KC) // 128

#define XROWB 144        // X row stride bytes (36 f32; 4-bank step, ldmatrix conflict-free)
#define VROWB 288        // VHL row stride bytes (72 f32; 8-bank step, LDS.64 conflict-free)

// ---- smem layout (bytes) ----
#define SM_XSQ    0                     // 64 f32
#define SM_RED    256                   // 4 x 64 f32
#define SM_TILES  1280
#define SLOT_X    0                     // 64 x 144 = 9216
#define SLOT_VHL  9216                  // 64 x 288 = 18432
#define SLOT_SZ   27648
#define SMEM_TOTAL (SM_TILES + STAGES * SLOT_SZ)   // 222464

__device__ float d_s[Fn];
__device__ float d_vhl[Kn * 2 * Fn];   // [64][2*4096]: (hi,lo) pairs along f

__device__ __forceinline__ uint32_t smem_u32(const void* p) {
    uint32_t a;
    asm("{ .reg .u64 t; cvta.to.shared.u64 t, %1; cvt.u32.u64 %0, t; }" : "=r"(a) : "l"(p));
    return a;
}
#define CP16(sa, gp) \
    asm volatile("cp.async.cg.shared.global [%0], [%1], 16;" :: "r"(sa), "l"(gp) : "memory")
#define CP_COMMIT() asm volatile("cp.async.commit_group;" ::: "memory")

__device__ __forceinline__ uint32_t to_tf32(float f) {
    uint32_t u;
    asm("cvt.rna.tf32.f32 %0, %1;" : "=r"(u) : "f"(f));
    return u;
}
__device__ __forceinline__ void mma_tf32(float* c, const uint32_t* a,
                                         uint32_t b0, uint32_t b1) {
    asm volatile("mma.sync.aligned.m16n8k8.row.col.f32.tf32.tf32.f32 "
                 "{%0,%1,%2,%3}, {%4,%5,%6,%7}, {%8,%9}, {%0,%1,%2,%3};"
                 : "+f"(c[0]), "+f"(c[1]), "+f"(c[2]), "+f"(c[3])
                 : "r"(a[0]), "r"(a[1]), "r"(a[2]), "r"(a[3]), "r"(b0), "r"(b1));
}
#define LDMATRIX4(r0, r1, r2, r3, addr) \
    asm volatile("ldmatrix.sync.aligned.m8n8.x4.shared.b16 {%0,%1,%2,%3}, [%4];" \
                 : "=r"(r0), "=r"(r1), "=r"(r2), "=r"(r3) : "r"(addr))

// ============ fused prep: transpose v into (hi,lo) pairs + s table ============
__global__ void prep_v(const float* __restrict__ v) {
    __shared__ float tile[64][65];
    const int f0 = blockIdx.x * 64;
    const int tid = threadIdx.x;
    for (int i = tid; i < 64 * 64; i += 256) {
        int fr = i >> 6, k = i & 63;
        tile[fr][k] = v[(size_t)(f0 + fr) * Kn + k];
    }
    __syncthreads();
    for (int i = tid; i < 64 * 64; i += 256) {
        int k = i >> 6, fr = i & 63;
        float val = tile[fr][k];
        float hi = __uint_as_float(to_tf32(val));
        float lo = __uint_as_float(to_tf32(val - hi));
        d_vhl[(size_t)k * (2 * Fn) + 2 * (f0 + fr)]     = hi;
        d_vhl[(size_t)k * (2 * Fn) + 2 * (f0 + fr) + 1] = lo;
    }
    const int fr = tid >> 2, q = tid & 3;
    float t = 0.f;
#pragma unroll
    for (int j = 0; j < 16; j++) {
        float val = tile[fr][q * 16 + j];
        t = fmaf(val, val, t);
    }
    t += __shfl_xor_sync(0xffffffffu, t, 1);
    t += __shfl_xor_sync(0xffffffffu, t, 2);
    if (q == 0) d_s[f0 + fr] = t;
}

// ================= main kernel =================
__device__ __forceinline__ void load_stage(const float* __restrict__ x, int row0,
                                           int t, uint32_t sb) {
    const int slot = t & (STAGES - 1);
    const int f0 = t * KC;
    const uint32_t base = sb + SM_TILES + slot * SLOT_SZ;
    const int tid = threadIdx.x;
    {   // X: 512 chunks of 16B
        const int r = tid >> 3, c = tid & 7;
        CP16(base + SLOT_X + (uint32_t)(r * XROWB + c * 16),
             x + (size_t)(row0 + r) * Fn + f0 + c * 4);
    }
#pragma unroll
    for (int j = 0; j < 2; j++) {   // VHL: 1024 chunks of 16B
        const int idx = tid + 512 * j;
        const int r = idx >> 4, c = idx & 15;
        CP16(base + SLOT_VHL + (uint32_t)(r * VROWB + c * 16),
             d_vhl + (size_t)r * (2 * Fn) + 2 * f0 + c * 4);
    }
}

__global__ void __launch_bounds__(NT, 1) fm_kernel(const float* __restrict__ x,
                                                   float* __restrict__ out) {
    extern __shared__ char smem[];
    const uint32_t sb = smem_u32(smem);
    const int tid = threadIdx.x;
    const int warp = tid >> 5, lane = tid & 31;
    const int wm = warp >> 2;        // 0..3 -> M offset 16*wm
    const int wn = warp & 3;         // 0..3 -> N offset 16*wn
    const int lr = lane >> 2, lc = lane & 3;
    const int row0 = blockIdx.x * MT;

    // preload stages 0..6
    for (int t = 0; t < STAGES - 1; t++) { load_stage(x, row0, t, sb); CP_COMMIT(); }

    float acc[2][4];
#pragma unroll
    for (int b = 0; b < 2; b++)
#pragma unroll
        for (int c = 0; c < 4; c++) acc[b][c] = 0.f;
    float xs[2] = {0.f, 0.f};

    // ldmatrix per-lane address offset within X slot
    const uint32_t a_lm = (uint32_t)((16 * wm + (lane & 7) + 8 * ((lane >> 3) & 1)) * XROWB
                                     + (lane >> 4) * 16);
    const uint32_t boff = (uint32_t)((16 * wn + lr) * VROWB + lc * 8);
    const bool do_xsq = (wn == 0);

    for (int t = 0; t < NTILES; t++) {
        const int slot = t & (STAGES - 1);
        if (t + STAGES - 1 < NTILES) asm volatile("cp.async.wait_group %0;" :: "n"(STAGES - 2) : "memory");
        else                         asm volatile("cp.async.wait_group 0;" ::: "memory");
        __syncthreads();
        if (t + STAGES - 1 < NTILES) { load_stage(x, row0, t + STAGES - 1, sb); CP_COMMIT(); }

        const uint32_t tb = sb + SM_TILES + slot * SLOT_SZ;
        const uint32_t xa = tb + SLOT_X + a_lm;
        const uint32_t vb = tb + SLOT_VHL + boff;
        const float* srow = d_s + t * KC + lc;

#pragma unroll
        for (int ks = 0; ks < 4; ks++) {
            uint32_t raw[4], ar[4];
            LDMATRIX4(raw[0], raw[1], raw[2], raw[3], xa + ks * 32);
            ar[0] = to_tf32(__uint_as_float(raw[0]));
            ar[1] = to_tf32(__uint_as_float(raw[1]));
            ar[2] = to_tf32(__uint_as_float(raw[2]));
            ar[3] = to_tf32(__uint_as_float(raw[3]));

            if (do_xsq) {
                float s0 = __ldg(srow + ks * 8);
                float s1 = __ldg(srow + ks * 8 + 4);
                float a0 = __uint_as_float(raw[0]), a1 = __uint_as_float(raw[1]);
                float a2 = __uint_as_float(raw[2]), a3 = __uint_as_float(raw[3]);
                xs[0] = fmaf(a0 * a0, s0, xs[0]);
                xs[0] = fmaf(a2 * a2, s1, xs[0]);
                xs[1] = fmaf(a1 * a1, s0, xs[1]);
                xs[1] = fmaf(a3 * a3, s1, xs[1]);
            }
#pragma unroll
            for (int nt = 0; nt < 2; nt++) {
                uint2 p0 = *(const uint2*)(uintptr_t)0;  // placeholder avoided below
                // pair loads: (hi,lo) for k = ks*8+lc and ks*8+lc+4
                uint32_t h0, l0, h1, l1;
                asm volatile("ld.shared.v2.b32 {%0,%1}, [%2];"
                             : "=r"(h0), "=r"(l0)
                             : "r"(vb + nt * (8 * VROWB) + ks * 64));
                asm volatile("ld.shared.v2.b32 {%0,%1}, [%2];"
                             : "=r"(h1), "=r"(l1)
                             : "r"(vb + nt * (8 * VROWB) + ks * 64 + 32));
                mma_tf32(acc[nt], ar, h0, h1);
                mma_tf32(acc[nt], ar, l0, l1);
                (void)p0;
            }
        }
    }

    // ---- epilogue ----
    float* xsq_s = (float*)(smem + SM_XSQ);
    if (do_xsq) {
#pragma unroll
        for (int i = 0; i < 2; i++) {
            float p = xs[i];
            p += __shfl_xor_sync(0xffffffffu, p, 1);
            p += __shfl_xor_sync(0xffffffffu, p, 2);
            if (lc == 0) xsq_s[16 * wm + 8 * i + lr] = p;
        }
    }

    float* red = (float*)(smem + SM_RED);
    {
        float p0 = acc[0][0] * acc[0][0] + acc[0][1] * acc[0][1]
                 + acc[1][0] * acc[1][0] + acc[1][1] * acc[1][1];
        float p1 = acc[0][2] * acc[0][2] + acc[0][3] * acc[0][3]
                 + acc[1][2] * acc[1][2] + acc[1][3] * acc[1][3];
        p0 += __shfl_xor_sync(0xffffffffu, p0, 1);
        p0 += __shfl_xor_sync(0xffffffffu, p0, 2);
        p1 += __shfl_xor_sync(0xffffffffu, p1, 1);
        p1 += __shfl_xor_sync(0xffffffffu, p1, 2);
        if (lc == 0) {
            int r = 16 * wm + lr;
            red[wn * 64 + r] = p0;
            red[wn * 64 + r + 8] = p1;
        }
    }
    __syncthreads();

    if (tid < MT) {
        float tot = red[tid] + red[64 + tid] + red[128 + tid] + red[192 + tid];
        out[row0 + tid] = 0.5f * (tot - xsq_s[tid]);
    }
}

extern "C" void kernel_launch(void* const* d_in, const int* in_sizes, int n_in,
                              void* d_out, int out_size) {
    const float* x = (const float*)d_in[0];   // [8192, 4096]
    const float* v = (const float*)d_in[1];   // [4096, 64]
    float* out = (float*)d_out;               // [8192, 1]

    cudaFuncSetAttribute(fm_kernel, cudaFuncAttributeMaxDynamicSharedMemorySize, SMEM_TOTAL);
    prep_v<<<Fn / 64, 256>>>(v);
    fm_kernel<<<Bn / MT, NT, SMEM_TOTAL>>>(x, out);
}

// round 7
// speedup vs baseline: 1.0502x; 1.0502x over previous
#include <cuda_runtime.h>
#include <cstdint>

#define Bn 8192
#define Fn 4096
#define Kn 64
#define MT 32            // rows per CTA -> 256 CTAs, 2 per SM
#define KC 32            // F-depth per stage
#define NT 256           // 8 warps: 2M x 4N
#define STAGES 4
#define NTILES (Fn / KC) // 128

#define XROWB 144        // X row stride bytes (36 f32)
#define VROWB 288        // VHL row stride bytes (72 f32)

// ---- smem layout (bytes) ----
#define SM_XSQ    0                     // 32 f32
#define SM_RED    128                   // 4 x 32 f32
#define SM_TILES  1024
#define SLOT_X    0                     // 32 x 144 = 4608
#define SLOT_VHL  4608                  // 64 x 288 = 18432
#define SLOT_SZ   23040
#define SMEM_TOTAL (SM_TILES + STAGES * SLOT_SZ)   // 93184 -> 2 CTAs/SM

__device__ float d_s[Fn];
__device__ float d_vhl[Kn * 2 * Fn];   // [64][2*4096]: (hi,lo) pairs along f

__device__ __forceinline__ uint32_t smem_u32(const void* p) {
    uint32_t a;
    asm("{ .reg .u64 t; cvta.to.shared.u64 t, %1; cvt.u32.u64 %0, t; }" : "=r"(a) : "l"(p));
    return a;
}
#define CP16(sa, gp) \
    asm volatile("cp.async.cg.shared.global [%0], [%1], 16;" :: "r"(sa), "l"(gp) : "memory")
#define CP_COMMIT() asm volatile("cp.async.commit_group;" ::: "memory")

__device__ __forceinline__ uint32_t to_tf32(float f) {
    uint32_t u;
    asm("cvt.rna.tf32.f32 %0, %1;" : "=r"(u) : "f"(f));
    return u;
}
__device__ __forceinline__ void mma_tf32(float* c, const uint32_t* a,
                                         uint32_t b0, uint32_t b1) {
    asm volatile("mma.sync.aligned.m16n8k8.row.col.f32.tf32.tf32.f32 "
                 "{%0,%1,%2,%3}, {%4,%5,%6,%7}, {%8,%9}, {%0,%1,%2,%3};"
                 : "+f"(c[0]), "+f"(c[1]), "+f"(c[2]), "+f"(c[3])
                 : "r"(a[0]), "r"(a[1]), "r"(a[2]), "r"(a[3]), "r"(b0), "r"(b1));
}
#define LDMATRIX4(r0, r1, r2, r3, addr) \
    asm volatile("ldmatrix.sync.aligned.m8n8.x4.shared.b16 {%0,%1,%2,%3}, [%4];" \
                 : "=r"(r0), "=r"(r1), "=r"(r2), "=r"(r3) : "r"(addr))

// ============ fused prep: transpose v into (hi,lo) pairs + s table ============
__global__ void prep_v(const float* __restrict__ v) {
    __shared__ float tile[64][65];
    const int f0 = blockIdx.x * 64;
    const int tid = threadIdx.x;
    for (int i = tid; i < 64 * 64; i += 256) {
        int fr = i >> 6, k = i & 63;
        tile[fr][k] = v[(size_t)(f0 + fr) * Kn + k];
    }
    __syncthreads();
    for (int i = tid; i < 64 * 64; i += 256) {
        int k = i >> 6, fr = i & 63;
        float val = tile[fr][k];
        float hi = __uint_as_float(to_tf32(val));
        float lo = __uint_as_float(to_tf32(val - hi));
        d_vhl[(size_t)k * (2 * Fn) + 2 * (f0 + fr)]     = hi;
        d_vhl[(size_t)k * (2 * Fn) + 2 * (f0 + fr) + 1] = lo;
    }
    const int fr = tid >> 2, q = tid & 3;
    float t = 0.f;
#pragma unroll
    for (int j = 0; j < 16; j++) {
        float val = tile[fr][q * 16 + j];
        t = fmaf(val, val, t);
    }
    t += __shfl_xor_sync(0xffffffffu, t, 1);
    t += __shfl_xor_sync(0xffffffffu, t, 2);
    if (q == 0) d_s[f0 + fr] = t;
}

// ================= main kernel =================
__device__ __forceinline__ void load_stage(const float* __restrict__ x, int row0,
                                           int t, uint32_t sb) {
    const int slot = t & (STAGES - 1);
    const int f0 = t * KC;
    const uint32_t base = sb + SM_TILES + slot * SLOT_SZ;
    const int tid = threadIdx.x;
    {   // X: 32 rows x 8 chunks = 256 chunks of 16B
        const int r = tid >> 3, c = tid & 7;
        CP16(base + SLOT_X + (uint32_t)(r * XROWB + c * 16),
             x + (size_t)(row0 + r) * Fn + f0 + c * 4);
    }
#pragma unroll
    for (int j = 0; j < 4; j++) {   // VHL: 64 rows x 16 chunks = 1024 chunks
        const int idx = tid + 256 * j;
        const int r = idx >> 4, c = idx & 15;
        CP16(base + SLOT_VHL + (uint32_t)(r * VROWB + c * 16),
             d_vhl + (size_t)r * (2 * Fn) + 2 * f0 + c * 4);
    }
}

__global__ void __launch_bounds__(NT, 2) fm_kernel(const float* __restrict__ x,
                                                   float* __restrict__ out) {
    extern __shared__ char smem[];
    const uint32_t sb = smem_u32(smem);
    const int tid = threadIdx.x;
    const int warp = tid >> 5, lane = tid & 31;
    const int wm = warp >> 2;        // 0..1 -> M offset 16*wm
    const int wn = warp & 3;         // 0..3 -> N offset 16*wn
    const int lr = lane >> 2, lc = lane & 3;
    const int row0 = blockIdx.x * MT;

    // preload stages 0..2
    for (int t = 0; t < STAGES - 1; t++) { load_stage(x, row0, t, sb); CP_COMMIT(); }

    float acc[2][4];
#pragma unroll
    for (int b = 0; b < 2; b++)
#pragma unroll
        for (int c = 0; c < 4; c++) acc[b][c] = 0.f;
    float xs[2] = {0.f, 0.f};

    const uint32_t a_lm = (uint32_t)((16 * wm + (lane & 7) + 8 * ((lane >> 3) & 1)) * XROWB
                                     + (lane >> 4) * 16);
    const uint32_t boff = (uint32_t)((16 * wn + lr) * VROWB + lc * 8);
    const bool do_xsq = (wn == 0);

    for (int t = 0; t < NTILES; t++) {
        const int slot = t & (STAGES - 1);
        if (t + STAGES - 1 < NTILES) asm volatile("cp.async.wait_group %0;" :: "n"(STAGES - 2) : "memory");
        else                         asm volatile("cp.async.wait_group 0;" ::: "memory");
        __syncthreads();
        if (t + STAGES - 1 < NTILES) { load_stage(x, row0, t + STAGES - 1, sb); CP_COMMIT(); }

        const uint32_t tb = sb + SM_TILES + slot * SLOT_SZ;
        const uint32_t xa = tb + SLOT_X + a_lm;
        const uint32_t vb = tb + SLOT_VHL + boff;
        const float* srow = d_s + t * KC + lc;

#pragma unroll
        for (int ks = 0; ks < 4; ks++) {
            uint32_t raw[4], ar[4];
            LDMATRIX4(raw[0], raw[1], raw[2], raw[3], xa + ks * 32);
            ar[0] = to_tf32(__uint_as_float(raw[0]));
            ar[1] = to_tf32(__uint_as_float(raw[1]));
            ar[2] = to_tf32(__uint_as_float(raw[2]));
            ar[3] = to_tf32(__uint_as_float(raw[3]));

            if (do_xsq) {
                float s0 = __ldg(srow + ks * 8);
                float s1 = __ldg(srow + ks * 8 + 4);
                float a0 = __uint_as_float(raw[0]), a1 = __uint_as_float(raw[1]);
                float a2 = __uint_as_float(raw[2]), a3 = __uint_as_float(raw[3]);
                xs[0] = fmaf(a0 * a0, s0, xs[0]);
                xs[0] = fmaf(a2 * a2, s1, xs[0]);
                xs[1] = fmaf(a1 * a1, s0, xs[1]);
                xs[1] = fmaf(a3 * a3, s1, xs[1]);
            }
#pragma unroll
            for (int nt = 0; nt < 2; nt++) {
                uint32_t h0, l0, h1, l1;
                asm volatile("ld.shared.v2.b32 {%0,%1}, [%2];"
                             : "=r"(h0), "=r"(l0)
                             : "r"(vb + nt * (8 * VROWB) + ks * 64));
                asm volatile("ld.shared.v2.b32 {%0,%1}, [%2];"
                             : "=r"(h1), "=r"(l1)
                             : "r"(vb + nt * (8 * VROWB) + ks * 64 + 32));
                mma_tf32(acc[nt], ar, h0, h1);
                mma_tf32(acc[nt], ar, l0, l1);
            }
        }
    }

    // ---- epilogue ----
    float* xsq_s = (float*)(smem + SM_XSQ);
    if (do_xsq) {
#pragma unroll
        for (int i = 0; i < 2; i++) {
            float p = xs[i];
            p += __shfl_xor_sync(0xffffffffu, p, 1);
            p += __shfl_xor_sync(0xffffffffu, p, 2);
            if (lc == 0) xsq_s[16 * wm + 8 * i + lr] = p;
        }
    }

    float* red = (float*)(smem + SM_RED);
    {
        float p0 = acc[0][0] * acc[0][0] + acc[0][1] * acc[0][1]
                 + acc[1][0] * acc[1][0] + acc[1][1] * acc[1][1];
        float p1 = acc[0][2] * acc[0][2] + acc[0][3] * acc[0][3]
                 + acc[1][2] * acc[1][2] + acc[1][3] * acc[1][3];
        p0 += __shfl_xor_sync(0xffffffffu, p0, 1);
        p0 += __shfl_xor_sync(0xffffffffu, p0, 2);
        p1 += __shfl_xor_sync(0xffffffffu, p1, 1);
        p1 += __shfl_xor_sync(0xffffffffu, p1, 2);
        if (lc == 0) {
            int r = 16 * wm + lr;
            red[wn * 32 + r] = p0;
            red[wn * 32 + r + 8] = p1;
        }
    }
    __syncthreads();

    if (tid < MT) {
        float tot = red[tid] + red[32 + tid] + red[64 + tid] + red[96 + tid];
        out[row0 + tid] = 0.5f * (tot - xsq_s[tid]);
    }
}

extern "C" void kernel_launch(void* const* d_in, const int* in_sizes, int n_in,
                              void* d_out, int out_size) {
    const float* x = (const float*)d_in[0];   // [8192, 4096]
    const float* v = (const float*)d_in[1];   // [4096, 64]
    float* out = (float*)d_out;               // [8192, 1]

    cudaFuncSetAttribute(fm_kernel, cudaFuncAttributeMaxDynamicSharedMemorySize, SMEM_TOTAL);
    prep_v<<<Fn / 64, 256>>>(v);
    fm_kernel<<<Bn / MT, NT, SMEM_TOTAL>>>(x, out);
}